// round 2
// baseline (speedup 1.0000x reference)
#include <cuda_runtime.h>
#include <cuda_bf16.h>

// NonSparsePLIF: v[t] = where(v[t-1]*d + x[t] >= 1.0, 0, v[t-1]*d + x[t])
// x_seq [T=16, 4194304] f32, decay [1] f32. HBM-bound streaming scan.
// R2: 2x float4 per thread (double MLP), __ldcs/__stcs streaming hints.

#define T_STEPS 16
#define SPATIAL 4194304            // 16*64*64*64
#define SPATIAL4 (SPATIAL / 4)     // 1048576 float4 per timestep plane
#define PER_THREAD 2
#define THREADS 256
#define VTH 1.0f

__global__ __launch_bounds__(THREADS) void plif_kernel(
    const float4* __restrict__ x,      // [T, SPATIAL4]
    const float* __restrict__ decay,   // [1]
    float4* __restrict__ out)          // [T, SPATIAL4]
{
    // Two float4 slots per thread, separated by blockDim so both are coalesced.
    const int base = blockIdx.x * (THREADS * PER_THREAD) + threadIdx.x;
    const int i0 = base;
    const int i1 = base + THREADS;

    const float d = decay[0];

    float4 v0 = make_float4(0.f, 0.f, 0.f, 0.f);
    float4 v1 = make_float4(0.f, 0.f, 0.f, 0.f);

#pragma unroll
    for (int t = 0; t < T_STEPS; ++t) {
        const size_t plane = (size_t)t * SPATIAL4;
        // Independent loads issue back-to-back -> 2x MLP vs one slot.
        const float4 x0 = __ldcs(&x[plane + i0]);
        const float4 x1 = __ldcs(&x[plane + i1]);

        v0.x = fmaf(v0.x, d, x0.x);
        v0.y = fmaf(v0.y, d, x0.y);
        v0.z = fmaf(v0.z, d, x0.z);
        v0.w = fmaf(v0.w, d, x0.w);
        v1.x = fmaf(v1.x, d, x1.x);
        v1.y = fmaf(v1.y, d, x1.y);
        v1.z = fmaf(v1.z, d, x1.z);
        v1.w = fmaf(v1.w, d, x1.w);

        v0.x = (v0.x >= VTH) ? 0.f : v0.x;
        v0.y = (v0.y >= VTH) ? 0.f : v0.y;
        v0.z = (v0.z >= VTH) ? 0.f : v0.z;
        v0.w = (v0.w >= VTH) ? 0.f : v0.w;
        v1.x = (v1.x >= VTH) ? 0.f : v1.x;
        v1.y = (v1.y >= VTH) ? 0.f : v1.y;
        v1.z = (v1.z >= VTH) ? 0.f : v1.z;
        v1.w = (v1.w >= VTH) ? 0.f : v1.w;

        __stcs(&out[plane + i0], v0);
        __stcs(&out[plane + i1], v1);
    }
}

extern "C" void kernel_launch(void* const* d_in, const int* in_sizes, int n_in,
                              void* d_out, int out_size)
{
    const float4* x   = (const float4*)d_in[0];
    const float*  dec = (const float*)d_in[1];
    float4*       out = (float4*)d_out;

    const int blocks = SPATIAL4 / (THREADS * PER_THREAD);  // 2048, exact
    plif_kernel<<<blocks, THREADS>>>(x, dec, out);
}